// round 13
// baseline (speedup 1.0000x reference)
#include <cuda_runtime.h>
#include <cuda_bf16.h>
#include <math.h>

// Problem constants
#define TSEQ 512
#define BATCH 128
#define DIMD 256
#define HID 128
#define G4 512      // 4*H
#define LBL 4
#define VOC 8000

typedef unsigned long long u64;

// ---------------- scratch (device globals; no allocation allowed) ----------------
__device__ float d_tab[(size_t)2 * VOC * G4];              // 33 MB: per-token input gates + biases
__device__ float d_hbuf[(size_t)TSEQ * BATCH * 2 * HID];   // 67 MB: [t][b][256] = concat(hf, hb)
__device__ float d_scores[(size_t)TSEQ * BATCH * LBL];     // 1 MB:  [t][b][4]

// ---------------- f32x2 packed math (register-only packing) ----------------
__device__ __forceinline__ u64 pack2(float x, float y) {
    u64 r; asm("mov.b64 %0, {%1,%2};" : "=l"(r) : "f"(x), "f"(y)); return r;
}
__device__ __forceinline__ float2 unpack2(u64 a) {
    float x, y; asm("mov.b64 {%0,%1}, %2;" : "=f"(x), "=f"(y) : "l"(a));
    return make_float2(x, y);
}
__device__ __forceinline__ void fma2(u64& d, u64 a, u64 b) {
    asm("fma.rn.f32x2 %0, %1, %2, %0;" : "+l"(d) : "l"(a), "l"(b));
}

__device__ __forceinline__ float sigm(float x) { return 1.f / (1.f + expf(-x)); }

// ============================================================================
// Kernel 1: vocabulary projection  tab[dir][v] = emb[v] @ W_ih^T + (b_ih+b_hh)
// ============================================================================
__global__ void __launch_bounds__(256) k_proj(
    const float* __restrict__ emb,
    const float* __restrict__ Wihf, const float* __restrict__ Wihb,
    const float* __restrict__ bihf, const float* __restrict__ bhhf,
    const float* __restrict__ bihb, const float* __restrict__ bhhb)
{
    __shared__ float As[16][128];   // [k][m]  m = vocab row
    __shared__ float Bs[16][128];   // [k][n]  n = gate row

    const int tid = threadIdx.x;
    const int mt  = blockIdx.x;          // vocab tile (0..62)
    const int nt  = blockIdx.y;          // 0..7
    const int dir = nt >> 2;
    const int gbase = (nt & 3) * 128;
    const float* __restrict__ W = dir ? Wihb : Wihf;

    const int tx = tid & 15, ty = tid >> 4;
    u64 acc[8][4];
#pragma unroll
    for (int i = 0; i < 8; ++i)
#pragma unroll
        for (int p = 0; p < 4; ++p) acc[i][p] = pack2(0.f, 0.f);

    for (int kt = 0; kt < 16; ++kt) {
        const int k0 = kt * 16;
        for (int e = tid; e < 512; e += 256) {
            const int row = e >> 2;            // 0..127
            const int kq  = (e & 3) * 4;       // 0,4,8,12
            int v = mt * 128 + row; if (v >= VOC) v = VOC - 1;   // clamp (reads only)
            const float4 av = *reinterpret_cast<const float4*>(
                &emb[(size_t)v * DIMD + k0 + kq]);
            As[kq + 0][row] = av.x; As[kq + 1][row] = av.y;
            As[kq + 2][row] = av.z; As[kq + 3][row] = av.w;
            const float4 bv = *reinterpret_cast<const float4*>(
                &W[(size_t)(gbase + row) * DIMD + k0 + kq]);
            Bs[kq + 0][row] = bv.x; Bs[kq + 1][row] = bv.y;
            Bs[kq + 2][row] = bv.z; Bs[kq + 3][row] = bv.w;
        }
        __syncthreads();
#pragma unroll
        for (int kk = 0; kk < 16; ++kk) {
            const float4 a0 = *reinterpret_cast<const float4*>(&As[kk][ty * 8]);
            const float4 a1 = *reinterpret_cast<const float4*>(&As[kk][ty * 8 + 4]);
            const float4 w0 = *reinterpret_cast<const float4*>(&Bs[kk][tx * 8]);
            const float4 w1 = *reinterpret_cast<const float4*>(&Bs[kk][tx * 8 + 4]);
            const u64 b0 = pack2(w0.x, w0.y);
            const u64 b1 = pack2(w0.z, w0.w);
            const u64 b2 = pack2(w1.x, w1.y);
            const u64 b3 = pack2(w1.z, w1.w);
            const float ar[8] = {a0.x, a0.y, a0.z, a0.w, a1.x, a1.y, a1.z, a1.w};
#pragma unroll
            for (int i = 0; i < 8; ++i) {
                const u64 ai = pack2(ar[i], ar[i]);
                fma2(acc[i][0], ai, b0);
                fma2(acc[i][1], ai, b1);
                fma2(acc[i][2], ai, b2);
                fma2(acc[i][3], ai, b3);
            }
        }
        __syncthreads();
    }

    const float* bi = dir ? bihb : bihf;
    const float* bh = dir ? bhhb : bhhf;
    float bias[8];
#pragma unroll
    for (int jj = 0; jj < 8; ++jj) {
        const int g = gbase + tx * 8 + jj;
        bias[jj] = bi[g] + bh[g];
    }
#pragma unroll
    for (int i = 0; i < 8; ++i) {
        const int v = mt * 128 + ty * 8 + i;
        if (v < VOC) {
            float* o = d_tab + (size_t)dir * ((size_t)VOC * G4)
                     + (size_t)v * G4 + gbase + tx * 8;
            const float2 v0 = unpack2(acc[i][0]);
            const float2 v1 = unpack2(acc[i][1]);
            const float2 v2 = unpack2(acc[i][2]);
            const float2 v3 = unpack2(acc[i][3]);
            float4 o0 = {v0.x + bias[0], v0.y + bias[1], v1.x + bias[2], v1.y + bias[3]};
            float4 o1 = {v2.x + bias[4], v2.y + bias[5], v3.x + bias[6], v3.y + bias[7]};
            *reinterpret_cast<float4*>(o)     = o0;
            *reinterpret_cast<float4*>(o + 4) = o1;
        }
    }
}

// ============================================================================
// Kernel 2: LSTM recurrence, dir-split + batch-paired, xor16 gate exchange.
// Row mapping: warp w, lane l -> unit m = w*16 + (l&15).
//   lanes 0..15:  rows {m, m+256}       = (i_m, g_m)
//   lanes 16..31: rows {m+128, m+384}   = (f_m, o_m)
// Gates activated in-lane, exchanged via shfl_xor(16) (same warp) -> NO g_s
// smem round-trip, ONE __syncthreads per step (h publish only).
// Lanes <16 update batch0 cell states, lanes >=16 update batch1.
// Weight split: cols 0..95 regs (2x48 u64), cols 96..127 smem (64 KB).
// ============================================================================
__global__ void __launch_bounds__(256, 1) k_lstm(
    const int* __restrict__ pad_seq, const int* __restrict__ lens,
    const float* __restrict__ Whhf, const float* __restrict__ Whhb)
{
    extern __shared__ char smp[];
    u64*   ws    = reinterpret_cast<u64*>(smp);                  // 16*512 u64 = 65536 B
    float* h0_s  = reinterpret_cast<float*>(smp + 65536);        // 128 floats
    float* h1_s  = reinterpret_cast<float*>(smp + 66048);        // 128 floats
    int*   toks0 = reinterpret_cast<int*>(smp + 66560);          // 512 ints
    int*   toks1 = reinterpret_cast<int*>(smp + 68608);          // 512 ints

    const int j   = threadIdx.x;          // 0..255
    const int b0  = blockIdx.x * 2;
    const int b1  = b0 + 1;
    const int dir = blockIdx.y;
    const int len0 = lens[b0];
    const int len1 = lens[b1];

    const int w = j >> 5, l = j & 31;
    const int m = w * 16 + (l & 15);              // hidden unit 0..127
    const bool lowh = (l < 16);
    const int rA = m + (lowh ? 0 : 128);          // i_m or f_m
    const int rB = rA + 256;                      // g_m or o_m

    toks0[j]       = pad_seq[b0 * TSEQ + j];
    toks0[j + 256] = pad_seq[b0 * TSEQ + j + 256];
    toks1[j]       = pad_seq[b1 * TSEQ + j];
    toks1[j + 256] = pad_seq[b1 * TSEQ + j + 256];

    const float* __restrict__ W = dir ? Whhb : Whhf;
    const float* wrowA = W + (size_t)rA * HID;
    const float* wrowB = W + (size_t)rB * HID;
    u64 wrA[48], wrB[48];
#pragma unroll
    for (int p = 0; p < 48; ++p) {
        const float2 wa = *reinterpret_cast<const float2*>(wrowA + 2 * p);
        wrA[p] = pack2(wa.x, wa.y);
        const float2 wb = *reinterpret_cast<const float2*>(wrowB + 2 * p);
        wrB[p] = pack2(wb.x, wb.y);
    }
#pragma unroll
    for (int p = 0; p < 16; ++p) {
        const float2 wa = *reinterpret_cast<const float2*>(wrowA + 96 + 2 * p);
        ws[p * 512 + rA] = pack2(wa.x, wa.y);
        const float2 wb = *reinterpret_cast<const float2*>(wrowB + 96 + 2 * p);
        ws[p * 512 + rB] = pack2(wb.x, wb.y);
    }
    if (j < HID) { h0_s[j] = 0.f; h1_s[j] = 0.f; }
    float c = 0.f;    // cell state: lanes<16 -> batch0 unit m; lanes>=16 -> batch1 unit m
    __syncthreads();                 // covers toks + ws + h_s

    const float* __restrict__ tab = d_tab + (size_t)dir * ((size_t)VOC * G4);
    int t = dir ? (TSEQ - 1) : 0;
    const int stp = dir ? -1 : 1;
    float xgA0 = tab[(size_t)toks0[t] * G4 + rA];
    float xgB0 = tab[(size_t)toks0[t] * G4 + rB];
    float xgA1 = tab[(size_t)toks1[t] * G4 + rA];
    float xgB1 = tab[(size_t)toks1[t] * G4 + rB];

    for (int it = 0; it < TSEQ; ++it) {
        const int tn = t + stp;
        float xgA0n = 0.f, xgB0n = 0.f, xgA1n = 0.f, xgB1n = 0.f;
        if (it < TSEQ - 1) {                          // prefetch next token rows
            const size_t base0 = (size_t)toks0[tn] * G4;
            const size_t base1 = (size_t)toks1[tn] * G4;
            xgA0n = tab[base0 + rA];
            xgB0n = tab[base0 + rB];
            xgA1n = tab[base1 + rA];
            xgB1n = tab[base1 + rB];
        }

        u64 accA0 = pack2(xgA0, 0.f);
        u64 accB0 = pack2(xgB0, 0.f);
        u64 accA1 = pack2(xgA1, 0.f);
        u64 accB1 = pack2(xgB1, 0.f);
        const ulonglong2* h02 = reinterpret_cast<const ulonglong2*>(h0_s);
        const ulonglong2* h12 = reinterpret_cast<const ulonglong2*>(h1_s);
#pragma unroll
        for (int q = 0; q < 24; ++q) {          // cols 0..95 from registers
            const ulonglong2 hv0 = h02[q];
            const ulonglong2 hv1 = h12[q];
            fma2(accA0, wrA[2 * q],     hv0.x);
            fma2(accA0, wrA[2 * q + 1], hv0.y);
            fma2(accB0, wrB[2 * q],     hv0.x);
            fma2(accB0, wrB[2 * q + 1], hv0.y);
            fma2(accA1, wrA[2 * q],     hv1.x);
            fma2(accA1, wrA[2 * q + 1], hv1.y);
            fma2(accB1, wrB[2 * q],     hv1.x);
            fma2(accB1, wrB[2 * q + 1], hv1.y);
        }
#pragma unroll
        for (int q = 0; q < 8; ++q) {           // cols 96..127 from shared
            const ulonglong2 hv0 = h02[24 + q];
            const ulonglong2 hv1 = h12[24 + q];
            const u64 wA0 = ws[(2 * q) * 512 + rA];
            const u64 wA1 = ws[(2 * q + 1) * 512 + rA];
            const u64 wB0 = ws[(2 * q) * 512 + rB];
            const u64 wB1 = ws[(2 * q + 1) * 512 + rB];
            fma2(accA0, wA0, hv0.x);
            fma2(accA0, wA1, hv0.y);
            fma2(accB0, wB0, hv0.x);
            fma2(accB0, wB1, hv0.y);
            fma2(accA1, wA0, hv1.x);
            fma2(accA1, wA1, hv1.y);
            fma2(accB1, wB0, hv1.x);
            fma2(accB1, wB1, hv1.y);
        }
        const float2 avA0 = unpack2(accA0);
        const float2 avB0 = unpack2(accB0);
        const float2 avA1 = unpack2(accA1);
        const float2 avB1 = unpack2(accB1);
        const float gA0 = avA0.x + avA0.y;       // raw row rA, batch0
        const float gB0 = avB0.x + avB0.y;       // raw row rB, batch0
        const float gA1 = avA1.x + avA1.y;
        const float gB1 = avB1.x + avB1.y;

        // in-lane activation (identical functions -> bit-identical gates)
        const float sA0 = sigm(gA0);                          // i (low) / f (high)
        const float sB0 = lowh ? tanhf(gB0) : sigm(gB0);      // g (low) / o (high)
        const float sA1 = sigm(gA1);
        const float sB1 = lowh ? tanhf(gB1) : sigm(gB1);

        // xor-16 exchange within warp (no barrier, no smem)
        const float xA0 = __shfl_xor_sync(0xffffffffu, sA0, 16);
        const float xB0 = __shfl_xor_sync(0xffffffffu, sB0, 16);
        const float xA1 = __shfl_xor_sync(0xffffffffu, sA1, 16);
        const float xB1 = __shfl_xor_sync(0xffffffffu, sB1, 16);

        if (lowh) {
            // batch0 unit m: i=sA0, g=sB0, f=xA0, o=xB0
            const float c2 = xA0 * c + sA0 * sB0;
            const float h2 = xB0 * tanhf(c2);
            const bool msk = (t < len0);
            d_hbuf[((size_t)t * BATCH + b0) * (2 * HID) + dir * HID + m] = msk ? h2 : 0.f;
            if (msk) { c = c2; h0_s[m] = h2; }
        } else {
            // batch1 unit m: f=sA1, o=sB1, i=xA1, g=xB1
            const float c2 = sA1 * c + xA1 * xB1;
            const float h2 = sB1 * tanhf(c2);
            const bool msk = (t < len1);
            d_hbuf[((size_t)t * BATCH + b1) * (2 * HID) + dir * HID + m] = msk ? h2 : 0.f;
            if (msk) { c = c2; h1_s[m] = h2; }
        }
        __syncthreads();            // single barrier: h publish -> next-step reads
        xgA0 = xgA0n; xgB0 = xgB0n; xgA1 = xgA1n; xgB1 = xgB1n;
        t = tn;
    }
}

// ============================================================================
// Kernel 3: emissions  scores[t][b][l] = h[t][b][:] @ W_lab[l][:] + b_lab[l]
// ============================================================================
__global__ void __launch_bounds__(256) k_emis(
    const float* __restrict__ Wlab, const float* __restrict__ blab)
{
    __shared__ float wl[LBL * DIMD];
    const int tid = threadIdx.x;
    for (int e = tid; e < LBL * DIMD; e += 256) wl[e] = Wlab[e];
    __syncthreads();

    const int wid = tid >> 5, lane = tid & 31;
    const int m = blockIdx.x * 8 + wid;        // m = t*128 + b
    const float* h = d_hbuf + (size_t)m * (2 * HID);

    float a0 = 0.f, a1 = 0.f, a2 = 0.f, a3 = 0.f;
#pragma unroll
    for (int cch = 0; cch < 2; ++cch) {
        const int k = cch * 128 + lane * 4;
        const float4 hv = *reinterpret_cast<const float4*>(h + k);
        a0 += hv.x * wl[k]       + hv.y * wl[k + 1]       + hv.z * wl[k + 2]       + hv.w * wl[k + 3];
        a1 += hv.x * wl[256 + k] + hv.y * wl[256 + k + 1] + hv.z * wl[256 + k + 2] + hv.w * wl[256 + k + 3];
        a2 += hv.x * wl[512 + k] + hv.y * wl[512 + k + 1] + hv.z * wl[512 + k + 2] + hv.w * wl[512 + k + 3];
        a3 += hv.x * wl[768 + k] + hv.y * wl[768 + k + 1] + hv.z * wl[768 + k + 2] + hv.w * wl[768 + k + 3];
    }
#pragma unroll
    for (int off = 16; off; off >>= 1) {
        a0 += __shfl_down_sync(0xffffffffu, a0, off);
        a1 += __shfl_down_sync(0xffffffffu, a1, off);
        a2 += __shfl_down_sync(0xffffffffu, a2, off);
        a3 += __shfl_down_sync(0xffffffffu, a3, off);
    }
    if (lane == 0) {
        float4 o = {a0 + blab[0], a1 + blab[1], a2 + blab[2], a3 + blab[3]};
        *reinterpret_cast<float4*>(d_scores + (size_t)m * 4) = o;
    }
}

// ============================================================================
// Kernel 4: Viterbi. One block per batch element (proven 49 us).
// ============================================================================
__global__ void __launch_bounds__(128) k_vit(
    const int* __restrict__ lens, const float* __restrict__ trans,
    const float* __restrict__ fromB, const float* __restrict__ toE,
    float* __restrict__ out)
{
    __shared__ float    s_sc[TSEQ * 4];     // 8 KB
    __shared__ unsigned s_bt[TSEQ];         // 2 KB
    __shared__ float    s_lab[TSEQ];        // 2 KB
    __shared__ float    tr[16], fb[4], te[4];

    const int tid = threadIdx.x;
    const int b = blockIdx.x;
    if (tid < 16) tr[tid] = trans[tid];
    if (tid < 4) { fb[tid] = fromB[tid]; te[tid] = toE[tid]; }

#pragma unroll
    for (int u = 0; u < 4; ++u) {
        const int t = tid + u * 128;
        const float4 v = *reinterpret_cast<const float4*>(
            d_scores + ((size_t)t * BATCH + b) * 4);
        *reinterpret_cast<float4*>(s_sc + t * 4) = v;
    }
    __syncthreads();

    if (tid == 0) {
        const int len = lens[b];
        float best[4];
        {
            const float4 e0 = *reinterpret_cast<const float4*>(s_sc);
            best[0] = fb[0] + e0.x; best[1] = fb[1] + e0.y;
            best[2] = fb[2] + e0.z; best[3] = fb[3] + e0.w;
        }
        for (int t = 1; t < len; ++t) {
            const float4 ev = *reinterpret_cast<const float4*>(s_sc + t * 4);
            const float e[4] = {ev.x, ev.y, ev.z, ev.w};
            unsigned w = 0;
            float nb[4];
#pragma unroll
            for (int l = 0; l < 4; ++l) {
                float mx = best[0] + tr[l];
                int ar = 0;
#pragma unroll
                for (int p = 1; p < 4; ++p) {
                    const float v = best[p] + tr[p * 4 + l];
                    if (v > mx) { mx = v; ar = p; }
                }
                nb[l] = mx + e[l];
                w |= (unsigned)ar << (2 * l);
            }
            s_bt[t] = w;
            best[0] = nb[0]; best[1] = nb[1]; best[2] = nb[2]; best[3] = nb[3];
        }
        const float fv[4] = {best[0] + te[0], best[1] + te[1], best[2] + te[2], best[3] + te[3]};
        int last = 0; float bm = fv[0];
#pragma unroll
        for (int l = 1; l < 4; ++l) if (fv[l] > bm) { bm = fv[l]; last = l; }

        int lab = last;
        for (int t = TSEQ - 1; t >= 0; --t) {
            float v;
            if (t >= len) v = 0.f;
            else if (t == len - 1) { lab = last; v = (float)lab; }
            else { lab = (int)((s_bt[t + 1] >> (2 * lab)) & 3u); v = (float)lab; }
            s_lab[t] = v;
        }
    }
    __syncthreads();

    {
        const float4* sl = reinterpret_cast<const float4*>(s_lab);
        float4* ob = reinterpret_cast<float4*>(out + (size_t)b * TSEQ);
        ob[tid] = sl[tid];
    }
}

// ============================================================================
extern "C" void kernel_launch(void* const* d_in, const int* in_sizes, int n_in,
                              void* d_out, int out_size)
{
    const int*   pad_seq = (const int*)  d_in[0];
    const int*   lens    = (const int*)  d_in[1];
    const float* emb     = (const float*)d_in[2];
    const float* Wihf    = (const float*)d_in[3];
    const float* Whhf    = (const float*)d_in[4];
    const float* bihf    = (const float*)d_in[5];
    const float* bhhf    = (const float*)d_in[6];
    const float* Wihb    = (const float*)d_in[7];
    const float* Whhb    = (const float*)d_in[8];
    const float* bihb    = (const float*)d_in[9];
    const float* bhhb    = (const float*)d_in[10];
    const float* Wlab    = (const float*)d_in[11];
    const float* blab    = (const float*)d_in[12];
    const float* trans   = (const float*)d_in[13];
    const float* fromB   = (const float*)d_in[14];
    const float* toE     = (const float*)d_in[15];
    float* out = (float*)d_out;

    const int lstm_smem = 65536 + 512 + 512 + 2048 + 2048;   // ws + h0 + h1 + toks = 70656
    cudaFuncSetAttribute(k_lstm, cudaFuncAttributeMaxDynamicSharedMemorySize, lstm_smem);

    k_proj<<<dim3(63, 8), 256>>>(emb, Wihf, Wihb, bihf, bhhf, bihb, bhhb);
    k_lstm<<<dim3(64, 2), 256, lstm_smem>>>(pad_seq, lens, Whhf, Whhb);
    k_emis<<<(TSEQ * BATCH) / 8, 256>>>(Wlab, blab);
    k_vit<<<BATCH, 128>>>(lens, trans, fromB, toE, out);
}

// round 14
// speedup vs baseline: 1.1160x; 1.1160x over previous
#include <cuda_runtime.h>
#include <cuda_bf16.h>
#include <math.h>

// Problem constants
#define TSEQ 512
#define BATCH 128
#define DIMD 256
#define HID 128
#define G4 512      // 4*H
#define LBL 4
#define VOC 8000

typedef unsigned long long u64;

// ---------------- scratch (device globals; no allocation allowed) ----------------
__device__ float d_tab[(size_t)2 * VOC * G4];              // 33 MB: per-token input gates + biases
__device__ float d_hbuf[(size_t)TSEQ * BATCH * 2 * HID];   // 67 MB: [t][b][256] = concat(hf, hb)
__device__ float d_scores[(size_t)TSEQ * BATCH * LBL];     // 1 MB:  [t][b][4]

// ---------------- f32x2 packed math (register-only packing) ----------------
__device__ __forceinline__ u64 pack2(float x, float y) {
    u64 r; asm("mov.b64 %0, {%1,%2};" : "=l"(r) : "f"(x), "f"(y)); return r;
}
__device__ __forceinline__ float2 unpack2(u64 a) {
    float x, y; asm("mov.b64 {%0,%1}, %2;" : "=f"(x), "=f"(y) : "l"(a));
    return make_float2(x, y);
}
__device__ __forceinline__ void fma2(u64& d, u64 a, u64 b) {
    asm("fma.rn.f32x2 %0, %1, %2, %0;" : "+l"(d) : "l"(a), "l"(b));
}

__device__ __forceinline__ float sigm(float x) { return 1.f / (1.f + expf(-x)); }

// ============================================================================
// Kernel 1: vocabulary projection  tab[dir][v] = emb[v] @ W_ih^T + (b_ih+b_hh)
// ============================================================================
__global__ void __launch_bounds__(256) k_proj(
    const float* __restrict__ emb,
    const float* __restrict__ Wihf, const float* __restrict__ Wihb,
    const float* __restrict__ bihf, const float* __restrict__ bhhf,
    const float* __restrict__ bihb, const float* __restrict__ bhhb)
{
    __shared__ float As[16][128];   // [k][m]  m = vocab row
    __shared__ float Bs[16][128];   // [k][n]  n = gate row

    const int tid = threadIdx.x;
    const int mt  = blockIdx.x;          // vocab tile (0..62)
    const int nt  = blockIdx.y;          // 0..7
    const int dir = nt >> 2;
    const int gbase = (nt & 3) * 128;
    const float* __restrict__ W = dir ? Wihb : Wihf;

    const int tx = tid & 15, ty = tid >> 4;
    u64 acc[8][4];
#pragma unroll
    for (int i = 0; i < 8; ++i)
#pragma unroll
        for (int p = 0; p < 4; ++p) acc[i][p] = pack2(0.f, 0.f);

    for (int kt = 0; kt < 16; ++kt) {
        const int k0 = kt * 16;
        for (int e = tid; e < 512; e += 256) {
            const int row = e >> 2;            // 0..127
            const int kq  = (e & 3) * 4;       // 0,4,8,12
            int v = mt * 128 + row; if (v >= VOC) v = VOC - 1;   // clamp (reads only)
            const float4 av = *reinterpret_cast<const float4*>(
                &emb[(size_t)v * DIMD + k0 + kq]);
            As[kq + 0][row] = av.x; As[kq + 1][row] = av.y;
            As[kq + 2][row] = av.z; As[kq + 3][row] = av.w;
            const float4 bv = *reinterpret_cast<const float4*>(
                &W[(size_t)(gbase + row) * DIMD + k0 + kq]);
            Bs[kq + 0][row] = bv.x; Bs[kq + 1][row] = bv.y;
            Bs[kq + 2][row] = bv.z; Bs[kq + 3][row] = bv.w;
        }
        __syncthreads();
#pragma unroll
        for (int kk = 0; kk < 16; ++kk) {
            const float4 a0 = *reinterpret_cast<const float4*>(&As[kk][ty * 8]);
            const float4 a1 = *reinterpret_cast<const float4*>(&As[kk][ty * 8 + 4]);
            const float4 w0 = *reinterpret_cast<const float4*>(&Bs[kk][tx * 8]);
            const float4 w1 = *reinterpret_cast<const float4*>(&Bs[kk][tx * 8 + 4]);
            const u64 b0 = pack2(w0.x, w0.y);
            const u64 b1 = pack2(w0.z, w0.w);
            const u64 b2 = pack2(w1.x, w1.y);
            const u64 b3 = pack2(w1.z, w1.w);
            const float ar[8] = {a0.x, a0.y, a0.z, a0.w, a1.x, a1.y, a1.z, a1.w};
#pragma unroll
            for (int i = 0; i < 8; ++i) {
                const u64 ai = pack2(ar[i], ar[i]);
                fma2(acc[i][0], ai, b0);
                fma2(acc[i][1], ai, b1);
                fma2(acc[i][2], ai, b2);
                fma2(acc[i][3], ai, b3);
            }
        }
        __syncthreads();
    }

    const float* bi = dir ? bihb : bihf;
    const float* bh = dir ? bhhb : bhhf;
    float bias[8];
#pragma unroll
    for (int jj = 0; jj < 8; ++jj) {
        const int g = gbase + tx * 8 + jj;
        bias[jj] = bi[g] + bh[g];
    }
#pragma unroll
    for (int i = 0; i < 8; ++i) {
        const int v = mt * 128 + ty * 8 + i;
        if (v < VOC) {
            float* o = d_tab + (size_t)dir * ((size_t)VOC * G4)
                     + (size_t)v * G4 + gbase + tx * 8;
            const float2 v0 = unpack2(acc[i][0]);
            const float2 v1 = unpack2(acc[i][1]);
            const float2 v2 = unpack2(acc[i][2]);
            const float2 v3 = unpack2(acc[i][3]);
            float4 o0 = {v0.x + bias[0], v0.y + bias[1], v1.x + bias[2], v1.y + bias[3]};
            float4 o1 = {v2.x + bias[4], v2.y + bias[5], v3.x + bias[6], v3.y + bias[7]};
            *reinterpret_cast<float4*>(o)     = o0;
            *reinterpret_cast<float4*>(o + 4) = o1;
        }
    }
}

// ============================================================================
// Kernel 2: LSTM recurrence, dir-split + batch-paired (R10 structure, proven
// 863us). Single change: weight split 96/32 -> 104/24 (cols 0..103 in regs,
// 2x52 u64; cols 104..127 in smem, 12 u64-slots x 512 = 48 KB). Cuts ws
// crossbar traffic 25% and LDS issue by 8/thread/step.
// ============================================================================
__global__ void __launch_bounds__(256, 1) k_lstm(
    const int* __restrict__ pad_seq, const int* __restrict__ lens,
    const float* __restrict__ Whhf, const float* __restrict__ Whhb)
{
    extern __shared__ char smp[];
    u64*   ws    = reinterpret_cast<u64*>(smp);                  // 12*512 u64 = 49152 B
    float* h0_s  = reinterpret_cast<float*>(smp + 49152);        // 128 floats
    float* h1_s  = reinterpret_cast<float*>(smp + 49664);        // 128 floats
    float* g0_s  = reinterpret_cast<float*>(smp + 50176);        // 512 floats
    float* g1_s  = reinterpret_cast<float*>(smp + 52224);        // 512 floats
    int*   toks0 = reinterpret_cast<int*>(smp + 54272);          // 512 ints
    int*   toks1 = reinterpret_cast<int*>(smp + 56320);          // 512 ints

    const int j   = threadIdx.x;          // 0..255
    const int b0  = blockIdx.x * 2;
    const int b1  = b0 + 1;
    const int dir = blockIdx.y;
    const int len0 = lens[b0];
    const int len1 = lens[b1];

    toks0[j]       = pad_seq[b0 * TSEQ + j];
    toks0[j + 256] = pad_seq[b0 * TSEQ + j + 256];
    toks1[j]       = pad_seq[b1 * TSEQ + j];
    toks1[j + 256] = pad_seq[b1 * TSEQ + j + 256];

    const float* __restrict__ W = dir ? Whhb : Whhf;
    const float* wrowA = W + (size_t)j * HID;            // row j
    const float* wrowB = W + (size_t)(j + 256) * HID;    // row j+256
    u64 wrA[52], wrB[52];
#pragma unroll
    for (int p = 0; p < 52; ++p) {
        const float2 wa = *reinterpret_cast<const float2*>(wrowA + 2 * p);
        wrA[p] = pack2(wa.x, wa.y);                      // cols 0..103
        const float2 wb = *reinterpret_cast<const float2*>(wrowB + 2 * p);
        wrB[p] = pack2(wb.x, wb.y);
    }
#pragma unroll
    for (int p = 0; p < 12; ++p) {
        const float2 wa = *reinterpret_cast<const float2*>(wrowA + 104 + 2 * p);
        ws[p * 512 + j] = pack2(wa.x, wa.y);             // cols 104..127
        const float2 wb = *reinterpret_cast<const float2*>(wrowB + 104 + 2 * p);
        ws[p * 512 + j + 256] = pack2(wb.x, wb.y);
    }
    if (j < HID) { h0_s[j] = 0.f; h1_s[j] = 0.f; }
    float c0 = 0.f, c1 = 0.f;
    __syncthreads();                 // covers toks + ws + h_s

    const float* __restrict__ tab = d_tab + (size_t)dir * ((size_t)VOC * G4);
    int t = dir ? (TSEQ - 1) : 0;
    const int stp = dir ? -1 : 1;
    float xgA0 = tab[(size_t)toks0[t] * G4 + j];
    float xgB0 = tab[(size_t)toks0[t] * G4 + j + 256];
    float xgA1 = tab[(size_t)toks1[t] * G4 + j];
    float xgB1 = tab[(size_t)toks1[t] * G4 + j + 256];

    for (int it = 0; it < TSEQ; ++it) {
        const int tn = t + stp;
        float xgA0n = 0.f, xgB0n = 0.f, xgA1n = 0.f, xgB1n = 0.f;
        if (it < TSEQ - 1) {                          // prefetch next token rows
            const size_t base0 = (size_t)toks0[tn] * G4;
            const size_t base1 = (size_t)toks1[tn] * G4;
            xgA0n = tab[base0 + j];
            xgB0n = tab[base0 + j + 256];
            xgA1n = tab[base1 + j];
            xgB1n = tab[base1 + j + 256];
        }

        u64 accA0 = pack2(xgA0, 0.f);
        u64 accB0 = pack2(xgB0, 0.f);
        u64 accA1 = pack2(xgA1, 0.f);
        u64 accB1 = pack2(xgB1, 0.f);
        const float4* h04 = reinterpret_cast<const float4*>(h0_s);
        const float4* h14 = reinterpret_cast<const float4*>(h1_s);
#pragma unroll
        for (int q = 0; q < 26; ++q) {          // cols 0..103 from registers
            const float4 hv0 = h04[q];
            const float4 hv1 = h14[q];
            const u64 h0xy = pack2(hv0.x, hv0.y);
            const u64 h0zw = pack2(hv0.z, hv0.w);
            const u64 h1xy = pack2(hv1.x, hv1.y);
            const u64 h1zw = pack2(hv1.z, hv1.w);
            fma2(accA0, wrA[2 * q],     h0xy);
            fma2(accA0, wrA[2 * q + 1], h0zw);
            fma2(accB0, wrB[2 * q],     h0xy);
            fma2(accB0, wrB[2 * q + 1], h0zw);
            fma2(accA1, wrA[2 * q],     h1xy);
            fma2(accA1, wrA[2 * q + 1], h1zw);
            fma2(accB1, wrB[2 * q],     h1xy);
            fma2(accB1, wrB[2 * q + 1], h1zw);
        }
#pragma unroll
        for (int q = 0; q < 6; ++q) {           // cols 104..127 from shared
            const float4 hv0 = h04[26 + q];
            const float4 hv1 = h14[26 + q];
            const u64 h0xy = pack2(hv0.x, hv0.y);
            const u64 h0zw = pack2(hv0.z, hv0.w);
            const u64 h1xy = pack2(hv1.x, hv1.y);
            const u64 h1zw = pack2(hv1.z, hv1.w);
            const u64 wA0 = ws[(2 * q) * 512 + j];
            const u64 wA1 = ws[(2 * q + 1) * 512 + j];
            const u64 wB0 = ws[(2 * q) * 512 + j + 256];
            const u64 wB1 = ws[(2 * q + 1) * 512 + j + 256];
            fma2(accA0, wA0, h0xy);
            fma2(accA0, wA1, h0zw);
            fma2(accB0, wB0, h0xy);
            fma2(accB0, wB1, h0zw);
            fma2(accA1, wA0, h1xy);
            fma2(accA1, wA1, h1zw);
            fma2(accB1, wB0, h1xy);
            fma2(accB1, wB1, h1zw);
        }
        const float2 avA0 = unpack2(accA0);
        const float2 avB0 = unpack2(accB0);
        const float2 avA1 = unpack2(accA1);
        const float2 avB1 = unpack2(accB1);
        const float gA0 = avA0.x + avA0.y;       // raw gate row j,     batch 0
        const float gB0 = avB0.x + avB0.y;       // raw gate row j+256, batch 0
        const float gA1 = avA1.x + avA1.y;
        const float gB1 = avB1.x + avB1.y;
        // pre-activate: rows 0..255 sigmoid; 256..383 tanh; 384..511 sigmoid
        g0_s[j] = sigm(gA0);
        g0_s[j + 256] = (j < 128) ? tanhf(gB0) : sigm(gB0);
        g1_s[j] = sigm(gA1);
        g1_s[j + 256] = (j < 128) ? tanhf(gB1) : sigm(gB1);
        __syncthreads();

        if (j < HID) {
            // batch 0
            {
                const float i_ = g0_s[j];
                const float f_ = g0_s[j + 128];
                const float tg = g0_s[j + 256];
                const float o_ = g0_s[j + 384];
                const float c2 = f_ * c0 + i_ * tg;
                const float h2 = o_ * tanhf(c2);
                const bool m = (t < len0);
                d_hbuf[((size_t)t * BATCH + b0) * (2 * HID) + dir * HID + j] = m ? h2 : 0.f;
                if (m) { c0 = c2; h0_s[j] = h2; }
            }
            // batch 1
            {
                const float i_ = g1_s[j];
                const float f_ = g1_s[j + 128];
                const float tg = g1_s[j + 256];
                const float o_ = g1_s[j + 384];
                const float c2 = f_ * c1 + i_ * tg;
                const float h2 = o_ * tanhf(c2);
                const bool m = (t < len1);
                d_hbuf[((size_t)t * BATCH + b1) * (2 * HID) + dir * HID + j] = m ? h2 : 0.f;
                if (m) { c1 = c2; h1_s[j] = h2; }
            }
        }
        __syncthreads();
        xgA0 = xgA0n; xgB0 = xgB0n; xgA1 = xgA1n; xgB1 = xgB1n;
        t = tn;
    }
}

// ============================================================================
// Kernel 3: emissions  scores[t][b][l] = h[t][b][:] @ W_lab[l][:] + b_lab[l]
// ============================================================================
__global__ void __launch_bounds__(256) k_emis(
    const float* __restrict__ Wlab, const float* __restrict__ blab)
{
    __shared__ float wl[LBL * DIMD];
    const int tid = threadIdx.x;
    for (int e = tid; e < LBL * DIMD; e += 256) wl[e] = Wlab[e];
    __syncthreads();

    const int wid = tid >> 5, lane = tid & 31;
    const int m = blockIdx.x * 8 + wid;        // m = t*128 + b
    const float* h = d_hbuf + (size_t)m * (2 * HID);

    float a0 = 0.f, a1 = 0.f, a2 = 0.f, a3 = 0.f;
#pragma unroll
    for (int cch = 0; cch < 2; ++cch) {
        const int k = cch * 128 + lane * 4;
        const float4 hv = *reinterpret_cast<const float4*>(h + k);
        a0 += hv.x * wl[k]       + hv.y * wl[k + 1]       + hv.z * wl[k + 2]       + hv.w * wl[k + 3];
        a1 += hv.x * wl[256 + k] + hv.y * wl[256 + k + 1] + hv.z * wl[256 + k + 2] + hv.w * wl[256 + k + 3];
        a2 += hv.x * wl[512 + k] + hv.y * wl[512 + k + 1] + hv.z * wl[512 + k + 2] + hv.w * wl[512 + k + 3];
        a3 += hv.x * wl[768 + k] + hv.y * wl[768 + k + 1] + hv.z * wl[768 + k + 2] + hv.w * wl[768 + k + 3];
    }
#pragma unroll
    for (int off = 16; off; off >>= 1) {
        a0 += __shfl_down_sync(0xffffffffu, a0, off);
        a1 += __shfl_down_sync(0xffffffffu, a1, off);
        a2 += __shfl_down_sync(0xffffffffu, a2, off);
        a3 += __shfl_down_sync(0xffffffffu, a3, off);
    }
    if (lane == 0) {
        float4 o = {a0 + blab[0], a1 + blab[1], a2 + blab[2], a3 + blab[3]};
        *reinterpret_cast<float4*>(d_scores + (size_t)m * 4) = o;
    }
}

// ============================================================================
// Kernel 4: Viterbi. One block per batch element (proven 49 us).
// ============================================================================
__global__ void __launch_bounds__(128) k_vit(
    const int* __restrict__ lens, const float* __restrict__ trans,
    const float* __restrict__ fromB, const float* __restrict__ toE,
    float* __restrict__ out)
{
    __shared__ float    s_sc[TSEQ * 4];     // 8 KB
    __shared__ unsigned s_bt[TSEQ];         // 2 KB
    __shared__ float    s_lab[TSEQ];        // 2 KB
    __shared__ float    tr[16], fb[4], te[4];

    const int tid = threadIdx.x;
    const int b = blockIdx.x;
    if (tid < 16) tr[tid] = trans[tid];
    if (tid < 4) { fb[tid] = fromB[tid]; te[tid] = toE[tid]; }

#pragma unroll
    for (int u = 0; u < 4; ++u) {
        const int t = tid + u * 128;
        const float4 v = *reinterpret_cast<const float4*>(
            d_scores + ((size_t)t * BATCH + b) * 4);
        *reinterpret_cast<float4*>(s_sc + t * 4) = v;
    }
    __syncthreads();

    if (tid == 0) {
        const int len = lens[b];
        float best[4];
        {
            const float4 e0 = *reinterpret_cast<const float4*>(s_sc);
            best[0] = fb[0] + e0.x; best[1] = fb[1] + e0.y;
            best[2] = fb[2] + e0.z; best[3] = fb[3] + e0.w;
        }
        for (int t = 1; t < len; ++t) {
            const float4 ev = *reinterpret_cast<const float4*>(s_sc + t * 4);
            const float e[4] = {ev.x, ev.y, ev.z, ev.w};
            unsigned w = 0;
            float nb[4];
#pragma unroll
            for (int l = 0; l < 4; ++l) {
                float mx = best[0] + tr[l];
                int ar = 0;
#pragma unroll
                for (int p = 1; p < 4; ++p) {
                    const float v = best[p] + tr[p * 4 + l];
                    if (v > mx) { mx = v; ar = p; }
                }
                nb[l] = mx + e[l];
                w |= (unsigned)ar << (2 * l);
            }
            s_bt[t] = w;
            best[0] = nb[0]; best[1] = nb[1]; best[2] = nb[2]; best[3] = nb[3];
        }
        const float fv[4] = {best[0] + te[0], best[1] + te[1], best[2] + te[2], best[3] + te[3]};
        int last = 0; float bm = fv[0];
#pragma unroll
        for (int l = 1; l < 4; ++l) if (fv[l] > bm) { bm = fv[l]; last = l; }

        int lab = last;
        for (int t = TSEQ - 1; t >= 0; --t) {
            float v;
            if (t >= len) v = 0.f;
            else if (t == len - 1) { lab = last; v = (float)lab; }
            else { lab = (int)((s_bt[t + 1] >> (2 * lab)) & 3u); v = (float)lab; }
            s_lab[t] = v;
        }
    }
    __syncthreads();

    {
        const float4* sl = reinterpret_cast<const float4*>(s_lab);
        float4* ob = reinterpret_cast<float4*>(out + (size_t)b * TSEQ);
        ob[tid] = sl[tid];
    }
}

// ============================================================================
extern "C" void kernel_launch(void* const* d_in, const int* in_sizes, int n_in,
                              void* d_out, int out_size)
{
    const int*   pad_seq = (const int*)  d_in[0];
    const int*   lens    = (const int*)  d_in[1];
    const float* emb     = (const float*)d_in[2];
    const float* Wihf    = (const float*)d_in[3];
    const float* Whhf    = (const float*)d_in[4];
    const float* bihf    = (const float*)d_in[5];
    const float* bhhf    = (const float*)d_in[6];
    const float* Wihb    = (const float*)d_in[7];
    const float* Whhb    = (const float*)d_in[8];
    const float* bihb    = (const float*)d_in[9];
    const float* bhhb    = (const float*)d_in[10];
    const float* Wlab    = (const float*)d_in[11];
    const float* blab    = (const float*)d_in[12];
    const float* trans   = (const float*)d_in[13];
    const float* fromB   = (const float*)d_in[14];
    const float* toE     = (const float*)d_in[15];
    float* out = (float*)d_out;

    const int lstm_smem = 49152 + 512 + 512 + 2048 + 2048 + 2048 + 2048;   // 58368
    cudaFuncSetAttribute(k_lstm, cudaFuncAttributeMaxDynamicSharedMemorySize, lstm_smem);

    k_proj<<<dim3(63, 8), 256>>>(emb, Wihf, Wihb, bihf, bhhf, bihb, bhhb);
    k_lstm<<<dim3(64, 2), 256, lstm_smem>>>(pad_seq, lens, Whhf, Whhb);
    k_emis<<<(TSEQ * BATCH) / 8, 256>>>(Wlab, blab);
    k_vit<<<BATCH, 128>>>(lens, trans, fromB, toE, out);
}